// round 2
// baseline (speedup 1.0000x reference)
#include <cuda_runtime.h>
#include <cuda_fp16.h>
#include <cstdint>

// ---------------------------------------------------------------------------
// Problem constants
// ---------------------------------------------------------------------------
#define BATCH    8192
#define IN_SIZE  512
#define OUT_SIZE 512
#define GRID_G   8
#define KDIM     (IN_SIZE * GRID_G)   // 4096

// GEMM tiling (Ampere-style: cp.async + ldmatrix + mma.sync -- plain sm_100 OK)
#define BM       128
#define BN       128
#define BK       64                    // 64 fp16 = 128 B rows
#define STAGES   4
#define NKC      (KDIM / BK)           // 64
#define A_BYTES  (BM * 128)            // 16384
#define B_BYTES  (BN * 128)            // 16384
#define STAGE_BYTES (A_BYTES + B_BYTES)
#define SMEM_TOTAL  (STAGES * STAGE_BYTES)   // 131072

// ---------------------------------------------------------------------------
// Scratch (device globals -- no cudaMalloc allowed)
// ---------------------------------------------------------------------------
__device__ __half g_S[(size_t)BATCH * KDIM];      // 64 MB: spline basis, fp16
__device__ __half g_B[(size_t)OUT_SIZE * KDIM];   // 4 MB: coeff*weight, fp16

__device__ __forceinline__ uint32_t smem_u32(const void* p) {
    uint32_t a;
    asm("{ .reg .u64 t; cvta.to.shared.u64 t, %1; cvt.u32.u64 %0, t; }"
        : "=r"(a) : "l"(p));
    return a;
}

// ---------------------------------------------------------------------------
// Kernel 1: B matrix prep  g_B[o, i*8+g] = coeff[o,i,g] * w[o,i]  (fp16)
// ---------------------------------------------------------------------------
__global__ void prep_kernel(const float* __restrict__ w, const float* __restrict__ coef) {
    int idx = blockIdx.x * blockDim.x + threadIdx.x;   // (o, i)
    if (idx >= OUT_SIZE * IN_SIZE) return;
    float wv = w[idx];
    const float4* c4 = reinterpret_cast<const float4*>(coef) + (size_t)idx * 2;
    float4 a = c4[0], b = c4[1];
    union { uint4 u; __half2 h[4]; } v;
    v.h[0] = __floats2half2_rn(a.x * wv, a.y * wv);
    v.h[1] = __floats2half2_rn(a.z * wv, a.w * wv);
    v.h[2] = __floats2half2_rn(b.x * wv, b.y * wv);
    v.h[3] = __floats2half2_rn(b.z * wv, b.w * wv);
    reinterpret_cast<uint4*>(g_B)[idx] = v.u;
}

// ---------------------------------------------------------------------------
// Kernel 2: spline basis  g_S[b, i*8+g] = basis_g(clamp(x[b,i]))  (fp16)
// De Boor, ORDER=3, 12 uniform centers: c[j] = -1 + j*(2/7)
// ---------------------------------------------------------------------------
__global__ void basis_kernel(const float* __restrict__ x) {
    int idx = blockIdx.x * blockDim.x + threadIdx.x;   // (b, i)
    if (idx >= BATCH * IN_SIZE) return;
    float xv = x[idx];
    xv = fminf(1.0f, fmaxf(-1.0f, xv));
    const float h = 2.0f / 7.0f;
    float c[12];
#pragma unroll
    for (int j = 0; j < 12; j++) c[j] = -1.0f + (float)j * h;
    float b[11];
#pragma unroll
    for (int j = 0; j < 11; j++)
        b[j] = (xv >= c[j] && xv < c[j + 1]) ? 1.0f : 0.0f;
#pragma unroll
    for (int k = 1; k <= 3; k++) {
        float inv = 1.0f / ((float)k * h);
#pragma unroll
        for (int j = 0; j <= 10 - k; j++)
            b[j] = (xv - c[j]) * inv * b[j] + (c[j + k + 1] - xv) * inv * b[j + 1];
    }
    union { uint4 u; __half2 hh[4]; } v;
    v.hh[0] = __floats2half2_rn(b[0], b[1]);
    v.hh[1] = __floats2half2_rn(b[2], b[3]);
    v.hh[2] = __floats2half2_rn(b[4], b[5]);
    v.hh[3] = __floats2half2_rn(b[6], b[7]);
    reinterpret_cast<uint4*>(g_S)[idx] = v.u;
}

// ---------------------------------------------------------------------------
// Kernel 3: mma.sync fp16 GEMM  out[8192,512] = S[8192,4096] @ B[512,4096]^T
// 128x128 CTA tile, BK=64, 4-stage cp.async pipeline, XOR-swizzled smem,
// 8 warps (2 M x 4 N), warp tile 64x32, m16n8k16 fp32-accumulate.
// ---------------------------------------------------------------------------
__global__ void __launch_bounds__(256, 1) bspline_gemm_kernel(float* __restrict__ out)
{
    extern __shared__ char smem[];
    const uint32_t sb = smem_u32(smem);
    const int tid  = threadIdx.x;
    const int lane = tid & 31;
    const int warp = tid >> 5;
    const int wm   = warp & 1;    // 0..1  (64 rows each)
    const int wn   = warp >> 1;   // 0..3  (32 cols each)

    const __half* gA = g_S + (size_t)blockIdx.y * BM * KDIM;
    const __half* gB = g_B + (size_t)blockIdx.x * BN * KDIM;

    // ---- stage loader: 1024 16B chunks per tile, 256 threads x 4 ----------
    auto load_stage = [&](int s, int kc) {
        const uint32_t base = sb + s * STAGE_BYTES;
#pragma unroll
        for (int t = 0; t < 4; t++) {
            int cid = tid + t * 256;                 // 0..1023
            int row = cid >> 3;                      // 0..127
            int cc  = cid & 7;                       // 16B chunk in row
            uint32_t soff = row * 128 + ((cc ^ (row & 7)) << 4);
            const __half* ga = gA + (size_t)row * KDIM + kc * BK + cc * 8;
            const __half* gb = gB + (size_t)row * KDIM + kc * BK + cc * 8;
            asm volatile("cp.async.cg.shared.global [%0], [%1], 16;"
                         :: "r"(base + soff), "l"(ga));
            asm volatile("cp.async.cg.shared.global [%0], [%1], 16;"
                         :: "r"(base + A_BYTES + soff), "l"(gb));
        }
    };

    // ---- prologue: fill STAGES-1 stages ------------------------------------
#pragma unroll
    for (int s = 0; s < STAGES - 1; s++) {
        load_stage(s, s);
        asm volatile("cp.async.commit_group;" ::: "memory");
    }

    float acc[4][4][4] = {};   // [mt][nt][4]

    for (int kc = 0; kc < NKC; kc++) {
        asm volatile("cp.async.wait_group %0;" :: "n"(STAGES - 2) : "memory");
        __syncthreads();

        // issue next stage (overwrites stage computed last iteration; guarded
        // by the syncthreads above). Always commit to keep wait_group counts.
        if (kc + STAGES - 1 < NKC)
            load_stage((kc + STAGES - 1) % STAGES, kc + STAGES - 1);
        asm volatile("cp.async.commit_group;" ::: "memory");

        const uint32_t sA = sb + (kc % STAGES) * STAGE_BYTES;
        const uint32_t sB = sA + A_BYTES;

#pragma unroll
        for (int kk = 0; kk < 4; kk++) {           // 4 x k16 per BK=64
            uint32_t ar[4][4];
            uint32_t br[4][2];
            // A fragments: 4 m16 tiles, ldmatrix.x4 each
#pragma unroll
            for (int mt = 0; mt < 4; mt++) {
                int row = wm * 64 + mt * 16 + (lane & 15);
                int kch = kk * 2 + (lane >> 4);
                uint32_t addr = sA + row * 128 + ((kch ^ (row & 7)) << 4);
                asm volatile("ldmatrix.sync.aligned.m8n8.x4.shared.b16 "
                             "{%0,%1,%2,%3}, [%4];"
                             : "=r"(ar[mt][0]), "=r"(ar[mt][1]),
                               "=r"(ar[mt][2]), "=r"(ar[mt][3])
                             : "r"(addr));
            }
            // B fragments: 2 x ldmatrix.x4, each yields two n8 frags
#pragma unroll
            for (int nt2 = 0; nt2 < 2; nt2++) {
                int row = wn * 32 + nt2 * 16 + (lane & 7) + ((lane >> 4) << 3);
                int kch = kk * 2 + ((lane >> 3) & 1);
                uint32_t addr = sB + row * 128 + ((kch ^ (row & 7)) << 4);
                asm volatile("ldmatrix.sync.aligned.m8n8.x4.shared.b16 "
                             "{%0,%1,%2,%3}, [%4];"
                             : "=r"(br[nt2 * 2][0]),     "=r"(br[nt2 * 2][1]),
                               "=r"(br[nt2 * 2 + 1][0]), "=r"(br[nt2 * 2 + 1][1])
                             : "r"(addr));
            }
#pragma unroll
            for (int mt = 0; mt < 4; mt++)
#pragma unroll
                for (int nt = 0; nt < 4; nt++)
                    asm volatile(
                        "mma.sync.aligned.m16n8k16.row.col.f32.f16.f16.f32 "
                        "{%0,%1,%2,%3}, {%4,%5,%6,%7}, {%8,%9}, {%0,%1,%2,%3};"
                        : "+f"(acc[mt][nt][0]), "+f"(acc[mt][nt][1]),
                          "+f"(acc[mt][nt][2]), "+f"(acc[mt][nt][3])
                        : "r"(ar[mt][0]), "r"(ar[mt][1]),
                          "r"(ar[mt][2]), "r"(ar[mt][3]),
                          "r"(br[nt][0]), "r"(br[nt][1]));
        }
    }

    // ---- epilogue: direct float2 stores ------------------------------------
#pragma unroll
    for (int mt = 0; mt < 4; mt++) {
        int r0 = blockIdx.y * BM + wm * 64 + mt * 16 + (lane >> 2);
#pragma unroll
        for (int nt = 0; nt < 4; nt++) {
            int c0 = blockIdx.x * BN + wn * 32 + nt * 8 + (lane & 3) * 2;
            float2 v0 = make_float2(acc[mt][nt][0], acc[mt][nt][1]);
            float2 v1 = make_float2(acc[mt][nt][2], acc[mt][nt][3]);
            *reinterpret_cast<float2*>(out + (size_t)r0 * OUT_SIZE + c0) = v0;
            *reinterpret_cast<float2*>(out + (size_t)(r0 + 8) * OUT_SIZE + c0) = v1;
        }
    }
}

// ---------------------------------------------------------------------------
// Host: kernel_launch (graph-capturable, allocation-free)
// ---------------------------------------------------------------------------
extern "C" void kernel_launch(void* const* d_in, const int* in_sizes, int n_in,
                              void* d_out, int out_size) {
    const float* x    = (const float*)d_in[0];
    const float* w    = (const float*)d_in[1];
    const float* coef = (const float*)d_in[2];
    float*       out  = (float*)d_out;

    prep_kernel<<<(OUT_SIZE * IN_SIZE + 255) / 256, 256>>>(w, coef);
    basis_kernel<<<(BATCH * IN_SIZE + 255) / 256, 256>>>(x);

    cudaFuncSetAttribute(bspline_gemm_kernel,
                         cudaFuncAttributeMaxDynamicSharedMemorySize, SMEM_TOTAL);
    dim3 grid(OUT_SIZE / BN, BATCH / BM);   // (4, 64) = 256 CTAs
    bspline_gemm_kernel<<<grid, 256, SMEM_TOTAL>>>(out);
}

// round 3
// speedup vs baseline: 1.0640x; 1.0640x over previous
#include <cuda_runtime.h>
#include <cuda_fp16.h>
#include <cstdint>

// ---------------------------------------------------------------------------
// Problem constants
// ---------------------------------------------------------------------------
#define BATCH    8192
#define IN_SIZE  512
#define OUT_SIZE 512
#define KDIM     (IN_SIZE * 8)        // 4096

// GEMM tiling (Ampere-style: cp.async + ldmatrix + mma.sync -- plain sm_100 OK)
#define BM       128
#define BN       128
#define BK       64                    // 64 fp16 = 128 B rows
#define STAGES   4
#define NKC      (KDIM / BK)           // 64 k-chunks per tile
#define NTILES_N (OUT_SIZE / BN)       // 4
#define NTILES_M (BATCH / BM)          // 64
#define TOTAL_UNITS (NTILES_M * NTILES_N * NKC)   // 16384 (tile x kchunk)
#define A_BYTES  (BM * 128)            // 16384
#define B_BYTES  (BN * 128)            // 16384
#define STAGE_BYTES (A_BYTES + B_BYTES)
#define SMEM_TOTAL  (STAGES * STAGE_BYTES)   // 131072

#define PREP_BLOCKS  ((OUT_SIZE * IN_SIZE) / 256)      // 1024
#define BASIS_BLOCKS ((BATCH * IN_SIZE) / 256)         // 16384

// ---------------------------------------------------------------------------
// Scratch (device globals -- no cudaMalloc allowed)
// ---------------------------------------------------------------------------
__device__ __half g_S[(size_t)BATCH * KDIM];      // 64 MB: spline basis, fp16
__device__ __half g_B[(size_t)OUT_SIZE * KDIM];   // 4 MB: coeff*weight, fp16

__device__ __forceinline__ uint32_t smem_u32(const void* p) {
    uint32_t a;
    asm("{ .reg .u64 t; cvta.to.shared.u64 t, %1; cvt.u32.u64 %0, t; }"
        : "=r"(a) : "l"(p));
    return a;
}

// ---------------------------------------------------------------------------
// Kernel 1: fused prep + basis (one launch)
//   blocks [0, PREP_BLOCKS):   g_B[o, i*8+g] = coeff[o,i,g] * w[o,i]
//   blocks [PREP_BLOCKS, ...): g_S[b, i*8+g] = basis_g(clamp(x[b,i]))
// ---------------------------------------------------------------------------
__global__ void prep_basis_kernel(const float* __restrict__ x,
                                  const float* __restrict__ w,
                                  const float* __restrict__ coef) {
    if (blockIdx.x < PREP_BLOCKS) {
        int idx = blockIdx.x * blockDim.x + threadIdx.x;   // (o, i)
        float wv = w[idx];
        const float4* c4 = reinterpret_cast<const float4*>(coef) + (size_t)idx * 2;
        float4 a = c4[0], b = c4[1];
        union { uint4 u; __half2 h[4]; } v;
        v.h[0] = __floats2half2_rn(a.x * wv, a.y * wv);
        v.h[1] = __floats2half2_rn(a.z * wv, a.w * wv);
        v.h[2] = __floats2half2_rn(b.x * wv, b.y * wv);
        v.h[3] = __floats2half2_rn(b.z * wv, b.w * wv);
        reinterpret_cast<uint4*>(g_B)[idx] = v.u;
    } else {
        int idx = (blockIdx.x - PREP_BLOCKS) * blockDim.x + threadIdx.x;  // (b, i)
        float xv = x[idx];
        xv = fminf(1.0f, fmaxf(-1.0f, xv));
        const float h = 2.0f / 7.0f;
        float c[12];
#pragma unroll
        for (int j = 0; j < 12; j++) c[j] = -1.0f + (float)j * h;
        float b[11];
#pragma unroll
        for (int j = 0; j < 11; j++)
            b[j] = (xv >= c[j] && xv < c[j + 1]) ? 1.0f : 0.0f;
#pragma unroll
        for (int k = 1; k <= 3; k++) {
            float inv = 1.0f / ((float)k * h);
#pragma unroll
            for (int j = 0; j <= 10 - k; j++)
                b[j] = (xv - c[j]) * inv * b[j] + (c[j + k + 1] - xv) * inv * b[j + 1];
        }
        union { uint4 u; __half2 hh[4]; } v;
        v.hh[0] = __floats2half2_rn(b[0], b[1]);
        v.hh[1] = __floats2half2_rn(b[2], b[3]);
        v.hh[2] = __floats2half2_rn(b[4], b[5]);
        v.hh[3] = __floats2half2_rn(b[6], b[7]);
        reinterpret_cast<uint4*>(g_S)[idx] = v.u;
    }
}

// ---------------------------------------------------------------------------
// Kernel 2: stream-K persistent GEMM
//   out[8192,512] += S[8192,4096] @ B[512,4096]^T   (out pre-zeroed)
// Global work = 16384 (tile,kchunk) units; each persistent CTA owns a
// contiguous range. cp.async pipeline flows continuously across tile
// boundaries; accumulators flushed by atomicAdd at segment ends.
// 128x128 tile, BK=64, 4-stage pipeline, XOR-swizzled smem,
// 8 warps (2 M x 4 N), warp tile 64x32, m16n8k16 fp32-accumulate.
// ---------------------------------------------------------------------------
__global__ void __launch_bounds__(256, 1) bspline_gemm_kernel(float* __restrict__ out,
                                                              int ncta)
{
    extern __shared__ char smem[];
    const uint32_t sb = smem_u32(smem);
    const int tid  = threadIdx.x;
    const int lane = tid & 31;
    const int warp = tid >> 5;
    const int wm   = warp & 1;    // 0..1  (64 rows each)
    const int wn   = warp >> 1;   // 0..3  (32 cols each)

    const int c0 = (int)((long long)blockIdx.x       * TOTAL_UNITS / ncta);
    const int c1 = (int)((long long)(blockIdx.x + 1) * TOTAL_UNITS / ncta);

    // ---- chunk loader keyed by global unit g: tile = g>>6, kchunk = g&63 ---
    auto load_chunk = [&](int g) {
        const int t     = g >> 6;
        const int kc    = g & 63;
        const int mtile = t >> 2;
        const int ntile = t & 3;
        const __half* gA = g_S + (size_t)mtile * BM * KDIM + kc * BK;
        const __half* gB = g_B + (size_t)ntile * BN * KDIM + kc * BK;
        const uint32_t base = sb + (g & 3) * STAGE_BYTES;
#pragma unroll
        for (int t4 = 0; t4 < 4; t4++) {
            int cid = tid + t4 * 256;                // 0..1023
            int row = cid >> 3;                      // 0..127
            int cc  = cid & 7;                       // 16B chunk in row
            uint32_t soff = row * 128 + ((cc ^ (row & 7)) << 4);
            const __half* ga = gA + (size_t)row * KDIM + cc * 8;
            const __half* gb = gB + (size_t)row * KDIM + cc * 8;
            asm volatile("cp.async.cg.shared.global [%0], [%1], 16;"
                         :: "r"(base + soff), "l"(ga));
            asm volatile("cp.async.cg.shared.global [%0], [%1], 16;"
                         :: "r"(base + A_BYTES + soff), "l"(gb));
        }
    };

    // ---- prologue: prefetch 3 chunks -------------------------------------
#pragma unroll
    for (int p = 0; p < STAGES - 1; p++) {
        if (c0 + p < c1) load_chunk(c0 + p);
        asm volatile("cp.async.commit_group;" ::: "memory");
    }

    float acc[4][4][4] = {};   // [mt][nt][4]

    for (int g = c0; g < c1; g++) {
        asm volatile("cp.async.wait_group %0;" :: "n"(STAGES - 2) : "memory");
        __syncthreads();

        if (g + STAGES - 1 < c1) load_chunk(g + STAGES - 1);
        asm volatile("cp.async.commit_group;" ::: "memory");

        const uint32_t sA = sb + (g & 3) * STAGE_BYTES;
        const uint32_t sB = sA + A_BYTES;

#pragma unroll
        for (int kk = 0; kk < 4; kk++) {           // 4 x k16 per BK=64
            uint32_t ar[4][4];
            uint32_t br[4][2];
#pragma unroll
            for (int mt = 0; mt < 4; mt++) {
                int row = wm * 64 + mt * 16 + (lane & 15);
                int kch = kk * 2 + (lane >> 4);
                uint32_t addr = sA + row * 128 + ((kch ^ (row & 7)) << 4);
                asm volatile("ldmatrix.sync.aligned.m8n8.x4.shared.b16 "
                             "{%0,%1,%2,%3}, [%4];"
                             : "=r"(ar[mt][0]), "=r"(ar[mt][1]),
                               "=r"(ar[mt][2]), "=r"(ar[mt][3])
                             : "r"(addr));
            }
#pragma unroll
            for (int nt2 = 0; nt2 < 2; nt2++) {
                int row = wn * 32 + nt2 * 16 + (lane & 7) + ((lane >> 4) << 3);
                int kch = kk * 2 + ((lane >> 3) & 1);
                uint32_t addr = sB + row * 128 + ((kch ^ (row & 7)) << 4);
                asm volatile("ldmatrix.sync.aligned.m8n8.x4.shared.b16 "
                             "{%0,%1,%2,%3}, [%4];"
                             : "=r"(br[nt2 * 2][0]),     "=r"(br[nt2 * 2][1]),
                               "=r"(br[nt2 * 2 + 1][0]), "=r"(br[nt2 * 2 + 1][1])
                             : "r"(addr));
            }
#pragma unroll
            for (int mt = 0; mt < 4; mt++)
#pragma unroll
                for (int nt = 0; nt < 4; nt++)
                    asm volatile(
                        "mma.sync.aligned.m16n8k16.row.col.f32.f16.f16.f32 "
                        "{%0,%1,%2,%3}, {%4,%5,%6,%7}, {%8,%9}, {%0,%1,%2,%3};"
                        : "+f"(acc[mt][nt][0]), "+f"(acc[mt][nt][1]),
                          "+f"(acc[mt][nt][2]), "+f"(acc[mt][nt][3])
                        : "r"(ar[mt][0]), "r"(ar[mt][1]),
                          "r"(ar[mt][2]), "r"(ar[mt][3]),
                          "r"(br[nt][0]), "r"(br[nt][1]));
        }

        // ---- segment flush: tile finished, or end of this CTA's range -----
        if (((g & 63) == 63) || (g == c1 - 1)) {
            const int t     = g >> 6;
            const int mtile = t >> 2;
            const int ntile = t & 3;
#pragma unroll
            for (int mt = 0; mt < 4; mt++) {
                int r0 = mtile * BM + wm * 64 + mt * 16 + (lane >> 2);
#pragma unroll
                for (int nt = 0; nt < 4; nt++) {
                    int cc = ntile * BN + wn * 32 + nt * 8 + (lane & 3) * 2;
                    float* p0 = out + (size_t)r0 * OUT_SIZE + cc;
                    float* p1 = out + (size_t)(r0 + 8) * OUT_SIZE + cc;
                    atomicAdd(p0,     acc[mt][nt][0]);
                    atomicAdd(p0 + 1, acc[mt][nt][1]);
                    atomicAdd(p1,     acc[mt][nt][2]);
                    atomicAdd(p1 + 1, acc[mt][nt][3]);
                    acc[mt][nt][0] = 0.f; acc[mt][nt][1] = 0.f;
                    acc[mt][nt][2] = 0.f; acc[mt][nt][3] = 0.f;
                }
            }
        }
    }
}

// ---------------------------------------------------------------------------
// Host: kernel_launch (graph-capturable, allocation-free)
// Host code runs once at capture; replay cost is just the graph nodes.
// ---------------------------------------------------------------------------
extern "C" void kernel_launch(void* const* d_in, const int* in_sizes, int n_in,
                              void* d_out, int out_size) {
    const float* x    = (const float*)d_in[0];
    const float* w    = (const float*)d_in[1];
    const float* coef = (const float*)d_in[2];
    float*       out  = (float*)d_out;

    int nsm = 148;
    cudaDeviceGetAttribute(&nsm, cudaDevAttrMultiProcessorCount, 0);

    // out is accumulated into via atomics -> must start at zero
    cudaMemsetAsync(out, 0, (size_t)BATCH * OUT_SIZE * sizeof(float));

    prep_basis_kernel<<<PREP_BLOCKS + BASIS_BLOCKS, 256>>>(x, w, coef);

    cudaFuncSetAttribute(bspline_gemm_kernel,
                         cudaFuncAttributeMaxDynamicSharedMemorySize, SMEM_TOTAL);
    bspline_gemm_kernel<<<nsm, 256, SMEM_TOTAL>>>(out, nsm);
}

// round 5
// speedup vs baseline: 1.1366x; 1.0682x over previous
#include <cuda_runtime.h>
#include <cuda_fp16.h>
#include <cstdint>

// ---------------------------------------------------------------------------
// Problem constants
// ---------------------------------------------------------------------------
#define BATCH    8192
#define IN_SIZE  512
#define OUT_SIZE 512
#define KDIM     (IN_SIZE * 8)        // 4096

// GEMM tiling
#define BM       128
#define BN       128
#define BK       64                    // 64 fp16 = 128 B rows
#define STAGES   4
#define NTILES_N (OUT_SIZE / BN)       // 4
#define NTILES_M (BATCH / BM)          // 64
#define NKC      (KDIM / BK)           // 64
#define TOTAL_UNITS (NTILES_M * NTILES_N * NKC)   // 16384
#define A_BYTES  (BM * 128)
#define B_BYTES  (BN * 128)
#define STAGE_BYTES (A_BYTES + B_BYTES)
#define SMEM_TOTAL  (STAGES * STAGE_BYTES)   // 131072

#define PREP_BLOCKS  ((OUT_SIZE * IN_SIZE) / 256)      // 1024
#define BASIS_BLOCKS ((BATCH * IN_SIZE) / 256)         // 16384

// ---------------------------------------------------------------------------
// Scratch (device globals -- no cudaMalloc allowed)
// ---------------------------------------------------------------------------
__device__ __half g_S[(size_t)BATCH * KDIM];      // 64 MB
__device__ __half g_B[(size_t)OUT_SIZE * KDIM];   // 4 MB

__device__ __forceinline__ uint32_t smem_u32(const void* p) {
    uint32_t a;
    asm("{ .reg .u64 t; cvta.to.shared.u64 t, %1; cvt.u32.u64 %0, t; }"
        : "=r"(a) : "l"(p));
    return a;
}

// ---------------------------------------------------------------------------
// Kernel 1: fused prep + basis
//   blocks [0, PREP_BLOCKS):   g_B[o, i*8+g] = coeff[o,i,g] * w[o,i]
//   blocks [PREP_BLOCKS, ...): g_S[b, i*8+g] = basis_g(clamp(x[b,i]))
// Basis via closed-form uniform cubic B-spline: for x in knot interval i
// (t = (x-c_i)/h), only basis i-3..i are nonzero with the 4 standard cubics.
// ---------------------------------------------------------------------------
__global__ void prep_basis_kernel(const float* __restrict__ x,
                                  const float* __restrict__ w,
                                  const float* __restrict__ coef) {
    if (blockIdx.x < PREP_BLOCKS) {
        int idx = blockIdx.x * blockDim.x + threadIdx.x;   // (o, i)
        float wv = w[idx];
        const float4* c4 = reinterpret_cast<const float4*>(coef) + (size_t)idx * 2;
        float4 a = c4[0], b = c4[1];
        union { uint4 u; __half2 h[4]; } v;
        v.h[0] = __floats2half2_rn(a.x * wv, a.y * wv);
        v.h[1] = __floats2half2_rn(a.z * wv, a.w * wv);
        v.h[2] = __floats2half2_rn(b.x * wv, b.y * wv);
        v.h[3] = __floats2half2_rn(b.z * wv, b.w * wv);
        reinterpret_cast<uint4*>(g_B)[idx] = v.u;
    } else {
        int idx = (blockIdx.x - PREP_BLOCKS) * blockDim.x + threadIdx.x;  // (b, i)
        float xv = x[idx];
        xv = fminf(1.0f, fmaxf(-1.0f, xv));
        float u = (xv + 1.0f) * 3.5f;          // / h, h = 2/7
        int i = min(7, (int)u);
        float t = u - (float)i;
        const float k6 = 1.0f / 6.0f;
        float t2 = t * t, t3 = t2 * t, omt = 1.0f - t;
        float v0 = t3 * k6;                                  // d = 0  (j == i)
        float v1 = (1.0f + 3.0f * (t + t2 - t3)) * k6;       // d = 1
        float v2 = (4.0f - 6.0f * t2 + 3.0f * t3) * k6;      // d = 2
        float v3 = omt * omt * omt * k6;                     // d = 3  (j == i-3)
        float o[8];
#pragma unroll
        for (int j = 0; j < 8; j++) {
            int d = i - j;
            o[j] = (d == 0) ? v0 : (d == 1) ? v1 : (d == 2) ? v2
                 : (d == 3) ? v3 : 0.0f;
        }
        union { uint4 uu; __half2 hh[4]; } v;
        v.hh[0] = __floats2half2_rn(o[0], o[1]);
        v.hh[1] = __floats2half2_rn(o[2], o[3]);
        v.hh[2] = __floats2half2_rn(o[4], o[5]);
        v.hh[3] = __floats2half2_rn(o[6], o[7]);
        reinterpret_cast<uint4*>(g_S)[idx] = v.uu;
    }
}

// ---------------------------------------------------------------------------
// Kernel 2: stream-K persistent GEMM with register-level fragment pipelining
//   out[8192,512] += S[8192,4096] @ B[512,4096]^T   (out pre-zeroed)
// wait_group(1)+syncthreads at iteration END => stages g and g+1 always
// visible, enabling cross-chunk fragment prefetch (tensor pipe never waits
// on ldmatrix except at the very first chunk).
// ---------------------------------------------------------------------------
__global__ void __launch_bounds__(256, 1) bspline_gemm_kernel(float* __restrict__ out,
                                                              int ncta)
{
    extern __shared__ char smem[];
    const uint32_t sb = smem_u32(smem);
    const int tid  = threadIdx.x;
    const int lane = tid & 31;
    const int warp = tid >> 5;
    const int wm   = warp & 1;    // 0..1  (64 rows)
    const int wn   = warp >> 1;   // 0..3  (32 cols)

    const int c0 = (int)((long long)blockIdx.x       * TOTAL_UNITS / ncta);
    const int c1 = (int)((long long)(blockIdx.x + 1) * TOTAL_UNITS / ncta);

    auto load_chunk = [&](int g) {
        const int t     = g >> 6;
        const int kc    = g & 63;
        const int mtile = t >> 2;
        const int ntile = t & 3;
        const __half* gA = g_S + (size_t)mtile * BM * KDIM + kc * BK;
        const __half* gB = g_B + (size_t)ntile * BN * KDIM + kc * BK;
        const uint32_t base = sb + (g & 3) * STAGE_BYTES;
#pragma unroll
        for (int t4 = 0; t4 < 4; t4++) {
            int cid = tid + t4 * 256;
            int row = cid >> 3;
            int cc  = cid & 7;
            uint32_t soff = row * 128 + ((cc ^ (row & 7)) << 4);
            const __half* ga = gA + (size_t)row * KDIM + cc * 8;
            const __half* gb = gB + (size_t)row * KDIM + cc * 8;
            asm volatile("cp.async.cg.shared.global [%0], [%1], 16;"
                         :: "r"(base + soff), "l"(ga));
            asm volatile("cp.async.cg.shared.global [%0], [%1], 16;"
                         :: "r"(base + A_BYTES + soff), "l"(gb));
        }
    };

    // fragment loader: chunk g, k16-step kk -> given register buffers
    auto load_frags = [&](int g, int kk, uint32_t (*ar)[4], uint32_t (*br)[2]) {
        const uint32_t sA = sb + (g & 3) * STAGE_BYTES;
        const uint32_t sB = sA + A_BYTES;
#pragma unroll
        for (int mt = 0; mt < 4; mt++) {
            int row = wm * 64 + mt * 16 + (lane & 15);
            int kch = kk * 2 + (lane >> 4);
            uint32_t addr = sA + row * 128 + ((kch ^ (row & 7)) << 4);
            asm volatile("ldmatrix.sync.aligned.m8n8.x4.shared.b16 "
                         "{%0,%1,%2,%3}, [%4];"
                         : "=r"(ar[mt][0]), "=r"(ar[mt][1]),
                           "=r"(ar[mt][2]), "=r"(ar[mt][3])
                         : "r"(addr));
        }
#pragma unroll
        for (int nt2 = 0; nt2 < 2; nt2++) {
            int row = wn * 32 + nt2 * 16 + (lane & 7) + ((lane >> 4) << 3);
            int kch = kk * 2 + ((lane >> 3) & 1);
            uint32_t addr = sB + row * 128 + ((kch ^ (row & 7)) << 4);
            asm volatile("ldmatrix.sync.aligned.m8n8.x4.shared.b16 "
                         "{%0,%1,%2,%3}, [%4];"
                         : "=r"(br[nt2 * 2][0]),     "=r"(br[nt2 * 2][1]),
                           "=r"(br[nt2 * 2 + 1][0]), "=r"(br[nt2 * 2 + 1][1])
                         : "r"(addr));
        }
    };

    // ---- prologue: prefetch 3 chunks, make stages c0 & c0+1 visible -------
#pragma unroll
    for (int p = 0; p < STAGES - 1; p++) {
        if (c0 + p < c1) load_chunk(c0 + p);
        asm volatile("cp.async.commit_group;" ::: "memory");
    }
    asm volatile("cp.async.wait_group 1;" ::: "memory");
    __syncthreads();

    uint32_t ar[2][4][4], br[2][4][2];
    float acc[4][4][4] = {};

    load_frags(c0, 0, ar[0], br[0]);

    for (int g = c0; g < c1; g++) {
        if (g + STAGES - 1 < c1) load_chunk(g + STAGES - 1);
        asm volatile("cp.async.commit_group;" ::: "memory");

#pragma unroll
        for (int kk = 0; kk < 4; kk++) {
            // prefetch next fragments (next kk, or next chunk's kk0)
            if (kk < 3)               load_frags(g,     kk + 1, ar[(kk + 1) & 1], br[(kk + 1) & 1]);
            else if (g + 1 < c1)      load_frags(g + 1, 0,      ar[0],            br[0]);
            const int b = kk & 1;
#pragma unroll
            for (int mt = 0; mt < 4; mt++)
#pragma unroll
                for (int nt = 0; nt < 4; nt++)
                    asm volatile(
                        "mma.sync.aligned.m16n8k16.row.col.f32.f16.f16.f32 "
                        "{%0,%1,%2,%3}, {%4,%5,%6,%7}, {%8,%9}, {%0,%1,%2,%3};"
                        : "+f"(acc[mt][nt][0]), "+f"(acc[mt][nt][1]),
                          "+f"(acc[mt][nt][2]), "+f"(acc[mt][nt][3])
                        : "r"(ar[b][mt][0]), "r"(ar[b][mt][1]),
                          "r"(ar[b][mt][2]), "r"(ar[b][mt][3]),
                          "r"(br[b][nt][0]), "r"(br[b][nt][1]));
        }

        // ---- segment flush: tile finished, or end of this CTA's range -----
        if (((g & 63) == 63) || (g == c1 - 1)) {
            const int t     = g >> 6;
            const int mtile = t >> 2;
            const int ntile = t & 3;
#pragma unroll
            for (int mt = 0; mt < 4; mt++) {
                int r0 = mtile * BM + wm * 64 + mt * 16 + (lane >> 2);
#pragma unroll
                for (int nt = 0; nt < 4; nt++) {
                    int cc = ntile * BN + wn * 32 + nt * 8 + (lane & 3) * 2;
                    float* p0 = out + (size_t)r0 * OUT_SIZE + cc;
                    float* p1 = out + (size_t)(r0 + 8) * OUT_SIZE + cc;
                    atomicAdd(p0,     acc[mt][nt][0]);
                    atomicAdd(p0 + 1, acc[mt][nt][1]);
                    atomicAdd(p1,     acc[mt][nt][2]);
                    atomicAdd(p1 + 1, acc[mt][nt][3]);
                    acc[mt][nt][0] = 0.f; acc[mt][nt][1] = 0.f;
                    acc[mt][nt][2] = 0.f; acc[mt][nt][3] = 0.f;
                }
            }
        }

        // make stage g+2 visible for next iteration; also guards the
        // overwrite of stage (g)&3 by next iteration's load_chunk.
        asm volatile("cp.async.wait_group 1;" ::: "memory");
        __syncthreads();
    }
}

// ---------------------------------------------------------------------------
// Host: kernel_launch (graph-capturable, allocation-free)
// ---------------------------------------------------------------------------
extern "C" void kernel_launch(void* const* d_in, const int* in_sizes, int n_in,
                              void* d_out, int out_size) {
    const float* x    = (const float*)d_in[0];
    const float* w    = (const float*)d_in[1];
    const float* coef = (const float*)d_in[2];
    float*       out  = (float*)d_out;

    int nsm = 148;
    cudaDeviceGetAttribute(&nsm, cudaDevAttrMultiProcessorCount, 0);

    cudaMemsetAsync(out, 0, (size_t)BATCH * OUT_SIZE * sizeof(float));

    prep_basis_kernel<<<PREP_BLOCKS + BASIS_BLOCKS, 256>>>(x, w, coef);

    cudaFuncSetAttribute(bspline_gemm_kernel,
                         cudaFuncAttributeMaxDynamicSharedMemorySize, SMEM_TOTAL);
    bspline_gemm_kernel<<<nsm, 256, SMEM_TOTAL>>>(out, nsm);
}